// round 2
// baseline (speedup 1.0000x reference)
#include <cuda_runtime.h>
#include <cuda_fp16.h>
#include <math.h>

#define BATCH 2
#define SEQ   4096
#define DIM   128
#define SCALE 0.125f   // 64^-0.5

// ---------------- device scratch (no allocations allowed) ----------------
__device__ float  g_W[640 * 128];            // rows: 0..383 qkv, 384..511 ff1, 512..639 ff2
__device__ float  g_q[BATCH * SEQ * DIM];    // [b][n][h*64+d]
__device__ float  g_k[BATCH * SEQ * DIM];
__device__ float  g_v[BATCH * SEQ * DIM];
__device__ float  g_sq[BATCH * SEQ];
__device__ __half g_dist[(size_t)BATCH * SEQ * SEQ];   // 67 MB fp16 distances
__device__ double g_sum_spe;
__device__ float  g_inv2s2_spe;
__device__ float  g_spa[64 * 64];            // spatial mask LUT by (|dx|,|dy|)
__device__ float  g_attn[BATCH * SEQ * DIM];

// ---------------- init ----------------
__global__ void k_init() { g_sum_spe = 0.0; }

// ---------------- weight norm: W = v * g / ||v||  (row-wise, in-dim 128) ----------------
__global__ void k_weights(const float* __restrict__ vq, const float* __restrict__ gq,
                          const float* __restrict__ v1, const float* __restrict__ g1,
                          const float* __restrict__ v2, const float* __restrict__ g2) {
    int r = blockIdx.x, t = threadIdx.x;
    const float* v; float g;
    if (r < 384)      { v = vq + r * 128;        g = gq[r]; }
    else if (r < 512) { v = v1 + (r - 384) * 128; g = g1[r - 384]; }
    else              { v = v2 + (r - 512) * 128; g = g2[r - 512]; }
    float val = v[t];
    float ss = val * val;
    #pragma unroll
    for (int o = 16; o; o >>= 1) ss += __shfl_xor_sync(0xffffffffu, ss, o);
    __shared__ float ws[4];
    if ((t & 31) == 0) ws[t >> 5] = ss;
    __syncthreads();
    float tot = ws[0] + ws[1] + ws[2] + ws[3];
    g_W[r * 128 + t] = val * (g / sqrtf(tot));
}

// ---------------- qkv projection + per-token ||x||^2 ----------------
__global__ void k_qkv(const float* __restrict__ x, const float* __restrict__ bq) {
    int token = blockIdx.x, t = threadIdx.x;
    __shared__ float xs[128];
    __shared__ float ws[4];
    float xv = x[token * 128 + t];
    xs[t] = xv;
    float ss = xv * xv;
    #pragma unroll
    for (int o = 16; o; o >>= 1) ss += __shfl_xor_sync(0xffffffffu, ss, o);
    if ((t & 31) == 0) ws[t >> 5] = ss;
    __syncthreads();
    if (t == 0) g_sq[token] = ws[0] + ws[1] + ws[2] + ws[3];
    #pragma unroll 1
    for (int c = t; c < 384; c += 128) {
        const float* w = g_W + c * 128;
        float acc = bq[c];
        #pragma unroll 16
        for (int k = 0; k < 128; k++) acc = fmaf(w[k], xs[k], acc);
        float* dst = (c < 128) ? g_q : ((c < 256) ? g_k : g_v);
        dst[token * 128 + (c & 127)] = acc;
    }
}

// ---------------- pairwise distance tiles + global sum ----------------
// grid (64 jt, 64 it, BATCH), 256 threads, dyn smem = 2*128*68*4 = 69632 B
__global__ void __launch_bounds__(256) k_dist(const float* __restrict__ x) {
    extern __shared__ float sm[];
    float* xiT = sm;              // [128][68] k-major
    float* xjT = sm + 128 * 68;
    int b  = blockIdx.z;
    int i0 = blockIdx.y * 64, j0 = blockIdx.x * 64;
    int tid = threadIdx.x;
    for (int idx = tid; idx < 64 * 128; idx += 256) {
        int r = idx >> 7, k = idx & 127;
        xiT[k * 68 + r] = x[(b * SEQ + i0 + r) * 128 + k];
        xjT[k * 68 + r] = x[(b * SEQ + j0 + r) * 128 + k];
    }
    __syncthreads();
    int ty = tid >> 4, tx = tid & 15;
    float acc[4][4] = {};
    #pragma unroll 4
    for (int k = 0; k < 128; k++) {
        float4 av = *(const float4*)&xiT[k * 68 + 4 * ty];
        float4 bv = *(const float4*)&xjT[k * 68 + 4 * tx];
        float a[4] = {av.x, av.y, av.z, av.w};
        float c[4] = {bv.x, bv.y, bv.z, bv.w};
        #pragma unroll
        for (int i = 0; i < 4; i++)
            #pragma unroll
            for (int j = 0; j < 4; j++) acc[i][j] = fmaf(a[i], c[j], acc[i][j]);
    }
    float sqi[4], sqj[4];
    #pragma unroll
    for (int i = 0; i < 4; i++) {
        sqi[i] = g_sq[b * SEQ + i0 + 4 * ty + i];
        sqj[i] = g_sq[b * SEQ + j0 + 4 * tx + i];
    }
    float lsum = 0.f;
    #pragma unroll
    for (int i = 0; i < 4; i++) {
        float dv[4];
        #pragma unroll
        for (int j = 0; j < 4; j++) {
            float d2 = sqi[i] + sqj[j] - 2.f * acc[i][j];
            float dd = sqrtf(fmaxf(d2, 0.f));
            dv[j] = dd; lsum += dd;
        }
        size_t base = ((size_t)(b * SEQ + i0 + 4 * ty + i)) * SEQ + j0 + 4 * tx;
        __half2* dp = (__half2*)(g_dist + base);
        dp[0] = __floats2half2_rn(dv[0], dv[1]);
        dp[1] = __floats2half2_rn(dv[2], dv[3]);
    }
    #pragma unroll
    for (int o = 16; o; o >>= 1) lsum += __shfl_xor_sync(0xffffffffu, lsum, o);
    __shared__ float rsum[8];
    if ((tid & 31) == 0) rsum[tid >> 5] = lsum;
    __syncthreads();
    if (tid == 0) {
        float tot = 0.f;
        #pragma unroll
        for (int w = 0; w < 8; w++) tot += rsum[w];
        atomicAdd(&g_sum_spe, (double)tot);
    }
}

// ---------------- finalize sigmas + spatial LUT ----------------
__global__ void k_finalize() {
    int t = threadIdx.x;
    __shared__ double red[256];
    double local = 0.0;
    for (int idx = t; idx < 64 * 64; idx += 256) {
        int adx = idx >> 6, ady = idx & 63;
        double cx = adx ? 2.0 * (64 - adx) : 64.0;
        double cy = ady ? 2.0 * (64 - ady) : 64.0;
        local += cx * cy * sqrt((double)(adx * adx + ady * ady));
    }
    red[t] = local; __syncthreads();
    for (int s = 128; s; s >>= 1) { if (t < s) red[t] += red[t + s]; __syncthreads(); }
    __shared__ float inv_spa;
    if (t == 0) {
        double sig_spa = red[0] / ((double)SEQ * (double)SEQ);
        inv_spa = (float)(1.0 / (2.0 * sig_spa * sig_spa));
        double sig_spe = g_sum_spe / ((double)BATCH * (double)SEQ * (double)SEQ);
        g_inv2s2_spe = (float)(1.0 / (2.0 * sig_spe * sig_spe));
    }
    __syncthreads();
    float iv = inv_spa;
    for (int idx = t; idx < 64 * 64; idx += 256) {
        int adx = idx >> 6, ady = idx & 63;
        g_spa[idx] = expf(-sqrtf((float)(adx * adx + ady * ady)) * iv);
    }
}

// ---------------- fused masked flash attention (both heads/CTA) ----------------
// grid (64 row-tiles, BATCH), 256 threads, dyn smem = 138240 B
__global__ void __launch_bounds__(256, 1) k_flash() {
    extern __shared__ float sm[];
    float* qiT = sm;                      // [128][68]
    float* kjT = qiT + 128 * 68;          // [128][68]
    float* vs  = kjT + 128 * 68;          // [64][132]
    float* ps  = vs + 64 * 132;           // [2][64][68]
    int b  = blockIdx.y;
    int i0 = blockIdx.x * 64;
    int tid = threadIdx.x;
    int ty = tid >> 4, tx = tid & 15;
    int myhead = tx >> 3;
    int d0 = tx * 8;

    for (int idx = tid; idx < 64 * 128; idx += 256) {
        int r = idx >> 7, k = idx & 127;
        qiT[k * 68 + r] = g_q[(b * SEQ + i0 + r) * 128 + k];
    }
    float inv_spe = g_inv2s2_spe;
    float o[4][8] = {};
    float mrun[2][4], lrun[2][4];
    #pragma unroll
    for (int h = 0; h < 2; h++)
        #pragma unroll
        for (int i = 0; i < 4; i++) { mrun[h][i] = -1e30f; lrun[h][i] = 0.f; }
    int ig[4], gxi[4], gyi[4];
    #pragma unroll
    for (int i = 0; i < 4; i++) {
        ig[i] = i0 + 4 * ty + i; gxi[i] = ig[i] >> 6; gyi[i] = ig[i] & 63;
    }

    for (int jt = 0; jt < 64; jt++) {
        int j0 = jt * 64;
        __syncthreads();   // protect kjT/vs from previous PV reads (covers qiT on jt=0 via next sync)
        for (int idx = tid; idx < 64 * 128; idx += 256) {
            int r = idx >> 7, k = idx & 127;
            kjT[k * 68 + r]  = g_k[(b * SEQ + j0 + r) * 128 + k];
            vs[r * 132 + k]  = g_v[(b * SEQ + j0 + r) * 128 + k];
        }
        __syncthreads();

        float s0[4][4] = {}, s1[4][4] = {};
        #pragma unroll 4
        for (int k = 0; k < 64; k++) {
            float4 av = *(const float4*)&qiT[k * 68 + 4 * ty];
            float4 bv = *(const float4*)&kjT[k * 68 + 4 * tx];
            float a[4] = {av.x, av.y, av.z, av.w};
            float c[4] = {bv.x, bv.y, bv.z, bv.w};
            #pragma unroll
            for (int i = 0; i < 4; i++)
                #pragma unroll
                for (int j = 0; j < 4; j++) s0[i][j] = fmaf(a[i], c[j], s0[i][j]);
        }
        #pragma unroll 4
        for (int k = 64; k < 128; k++) {
            float4 av = *(const float4*)&qiT[k * 68 + 4 * ty];
            float4 bv = *(const float4*)&kjT[k * 68 + 4 * tx];
            float a[4] = {av.x, av.y, av.z, av.w};
            float c[4] = {bv.x, bv.y, bv.z, bv.w};
            #pragma unroll
            for (int i = 0; i < 4; i++)
                #pragma unroll
                for (int j = 0; j < 4; j++) s1[i][j] = fmaf(a[i], c[j], s1[i][j]);
        }

        // combined spectral * spatial mask for the 4x4 microtile
        float wm[4][4];
        #pragma unroll
        for (int i = 0; i < 4; i++) {
            size_t base = ((size_t)(b * SEQ + ig[i])) * SEQ + j0 + 4 * tx;
            const __half2* dp = (const __half2*)(g_dist + base);
            __half2 h0 = dp[0], h1 = dp[1];
            float dv[4] = { __low2float(h0), __high2float(h0),
                            __low2float(h1), __high2float(h1) };
            #pragma unroll
            for (int j = 0; j < 4; j++) {
                int jg = j0 + 4 * tx + j;
                int adx = abs(gxi[i] - (jg >> 6));
                int ady = abs(gyi[i] - (jg & 63));
                float spa = __ldg(&g_spa[adx * 64 + ady]);
                wm[i][j] = spa * __expf(-dv[j] * inv_spe);
            }
        }

        // online softmax per (head, row)
        #pragma unroll
        for (int h = 0; h < 2; h++) {
            float (*sp)[4] = h ? s1 : s0;
            #pragma unroll
            for (int i = 0; i < 4; i++) {
                float p[4]; float mx = -1e30f;
                #pragma unroll
                for (int j = 0; j < 4; j++) {
                    float sc = sp[i][j] * SCALE * wm[i][j];
                    p[j] = sc; mx = fmaxf(mx, sc);
                }
                #pragma unroll
                for (int off = 8; off; off >>= 1)
                    mx = fmaxf(mx, __shfl_xor_sync(0xffffffffu, mx, off));
                float mold = mrun[h][i];
                float mnew = fmaxf(mold, mx);
                float corr = __expf(mold - mnew);
                float rs = 0.f;
                #pragma unroll
                for (int j = 0; j < 4; j++) { p[j] = __expf(p[j] - mnew); rs += p[j]; }
                #pragma unroll
                for (int off = 8; off; off >>= 1)
                    rs += __shfl_xor_sync(0xffffffffu, rs, off);
                lrun[h][i] = lrun[h][i] * corr + rs;
                mrun[h][i] = mnew;
                float* pr = ps + (h * 64 + 4 * ty + i) * 68 + 4 * tx;
                pr[0] = p[0]; pr[1] = p[1]; pr[2] = p[2]; pr[3] = p[3];
                if (myhead == h) {
                    #pragma unroll
                    for (int d = 0; d < 8; d++) o[i][d] *= corr;
                }
            }
        }
        __syncthreads();

        // PV: o[r][d] += P[my head][r][k] * V[k][d]
        const float* psh = ps + myhead * 64 * 68;
        #pragma unroll 4
        for (int k = 0; k < 64; k++) {
            float4 v0 = *(const float4*)&vs[k * 132 + d0];
            float4 v1 = *(const float4*)&vs[k * 132 + d0 + 4];
            #pragma unroll
            for (int i = 0; i < 4; i++) {
                float pv = psh[(4 * ty + i) * 68 + k];
                o[i][0] = fmaf(pv, v0.x, o[i][0]);
                o[i][1] = fmaf(pv, v0.y, o[i][1]);
                o[i][2] = fmaf(pv, v0.z, o[i][2]);
                o[i][3] = fmaf(pv, v0.w, o[i][3]);
                o[i][4] = fmaf(pv, v1.x, o[i][4]);
                o[i][5] = fmaf(pv, v1.y, o[i][5]);
                o[i][6] = fmaf(pv, v1.z, o[i][6]);
                o[i][7] = fmaf(pv, v1.w, o[i][7]);
            }
        }
    }

    #pragma unroll
    for (int i = 0; i < 4; i++) {
        float linv = 1.f / lrun[myhead][i];
        float* dst = g_attn + (b * SEQ + ig[i]) * 128 + d0;
        #pragma unroll
        for (int d = 0; d < 8; d++) dst[d] = o[i][d] * linv;
    }
}

// ---------------- fused FFN: wn-linear -> exact GELU -> wn-linear ----------------
__global__ void k_ff(const float* __restrict__ b1, const float* __restrict__ b2,
                     float* __restrict__ out) {
    int token = blockIdx.x, t = threadIdx.x;
    __shared__ float s0[128], s1[128];
    s0[t] = g_attn[token * 128 + t];
    __syncthreads();
    const float* w1 = g_W + (384 + t) * 128;
    float acc = b1[t];
    #pragma unroll 16
    for (int k = 0; k < 128; k++) acc = fmaf(w1[k], s0[k], acc);
    s1[t] = 0.5f * acc * (1.0f + erff(acc * 0.70710678118654752f));
    __syncthreads();
    const float* w2 = g_W + (512 + t) * 128;
    float acc2 = b2[t];
    #pragma unroll 16
    for (int k = 0; k < 128; k++) acc2 = fmaf(w2[k], s1[k], acc2);
    out[token * 128 + t] = acc2;
}

// ---------------- launch ----------------
extern "C" void kernel_launch(void* const* d_in, const int* in_sizes, int n_in,
                              void* d_out, int out_size) {
    const float* x     = (const float*)d_in[0];
    const float* v_qkv = (const float*)d_in[1];
    const float* g_qkv = (const float*)d_in[2];
    const float* b_qkv = (const float*)d_in[3];
    const float* v_ff1 = (const float*)d_in[4];
    const float* g_ff1 = (const float*)d_in[5];
    const float* b_ff1 = (const float*)d_in[6];
    const float* v_ff2 = (const float*)d_in[7];
    const float* g_ff2 = (const float*)d_in[8];
    const float* b_ff2 = (const float*)d_in[9];
    float* out = (float*)d_out;

    cudaFuncSetAttribute(k_dist,  cudaFuncAttributeMaxDynamicSharedMemorySize, 2 * 128 * 68 * 4);
    cudaFuncSetAttribute(k_flash, cudaFuncAttributeMaxDynamicSharedMemorySize,
                         (128 * 68 + 128 * 68 + 64 * 132 + 2 * 64 * 68) * 4);

    k_init<<<1, 1>>>();
    k_weights<<<640, 128>>>(v_qkv, g_qkv, v_ff1, g_ff1, v_ff2, g_ff2);
    k_qkv<<<BATCH * SEQ, 128>>>(x, b_qkv);
    k_dist<<<dim3(64, 64, BATCH), 256, 2 * 128 * 68 * 4>>>(x);
    k_finalize<<<1, 256>>>();
    k_flash<<<dim3(64, BATCH), 256, (128 * 68 + 128 * 68 + 64 * 132 + 2 * 64 * 68) * 4>>>();
    k_ff<<<BATCH * SEQ, 128>>>(b_ff1, b_ff2, out);
}

// round 3
// speedup vs baseline: 2.6270x; 2.6270x over previous
#include <cuda_runtime.h>
#include <cuda_fp16.h>
#include <math.h>

#define BATCH 2
#define SEQ   4096
#define DIM   128
#define SCALE 0.125f   // 64^-0.5

// ---------------- device scratch (no allocations allowed) ----------------
__device__ float  g_W[640 * 128];            // rows: 0..383 qkv, 384..511 ff1, 512..639 ff2
__device__ float  g_q[BATCH * SEQ * DIM];    // [b][n][h*64+d]; reused as h1 after flash
__device__ float  g_k[BATCH * SEQ * DIM];
__device__ float  g_v[BATCH * SEQ * DIM];
__device__ float  g_sq[BATCH * SEQ];
__device__ __half g_dist[(size_t)BATCH * SEQ * SEQ];   // 67 MB fp16 distances
__device__ double g_sum_spe;
__device__ float  g_inv2s2_spe;
__device__ float  g_spa[64 * 64];            // spatial mask LUT by (|dx|,|dy|)
__device__ float  g_attn[BATCH * SEQ * DIM];

// ---------------- init ----------------
__global__ void k_init() { g_sum_spe = 0.0; }

// ---------------- weight norm: W = v * g / ||v||  (row-wise, in-dim 128) ----------------
__global__ void k_weights(const float* __restrict__ vq, const float* __restrict__ gq,
                          const float* __restrict__ v1, const float* __restrict__ g1,
                          const float* __restrict__ v2, const float* __restrict__ g2) {
    int r = blockIdx.x, t = threadIdx.x;
    const float* v; float g;
    if (r < 384)      { v = vq + r * 128;        g = gq[r]; }
    else if (r < 512) { v = v1 + (r - 384) * 128; g = g1[r - 384]; }
    else              { v = v2 + (r - 512) * 128; g = g2[r - 512]; }
    float val = v[t];
    float ss = val * val;
    #pragma unroll
    for (int o = 16; o; o >>= 1) ss += __shfl_xor_sync(0xffffffffu, ss, o);
    __shared__ float ws[4];
    if ((t & 31) == 0) ws[t >> 5] = ss;
    __syncthreads();
    float tot = ws[0] + ws[1] + ws[2] + ws[3];
    g_W[r * 128 + t] = val * (g / sqrtf(tot));
}

// ---------------- per-token ||x||^2 (one warp per token) ----------------
__global__ void k_sq(const float* __restrict__ x) {
    int token = blockIdx.x * 8 + (threadIdx.x >> 5);
    int lane  = threadIdx.x & 31;
    const float4* xp = (const float4*)(x + token * 128);
    float4 a = xp[lane];
    float ss = a.x * a.x + a.y * a.y + a.z * a.z + a.w * a.w;
    #pragma unroll
    for (int o = 16; o; o >>= 1) ss += __shfl_xor_sync(0xffffffffu, ss, o);
    if (lane == 0) g_sq[token] = ss;
}

// ---------------- tiled projection GEMM: OUT[t][c] = sum_k A[t][k]*W[c][k] + bias[c]
// block = 64 tokens x 64 cols, 256 threads, 4x4 microtile, dyn smem 69632 B
// mode 0: qkv scatter to g_q/g_k/g_v; mode 1: GELU -> g_q (h1); mode 2: plain -> out
__global__ void __launch_bounds__(256) k_gemm64(const float* __restrict__ A,
                                                const float* __restrict__ Wrows,
                                                const float* __restrict__ bias,
                                                float* __restrict__ out, int mode) {
    extern __shared__ float sm[];
    float* aT = sm;              // [128k][68]
    float* wT = sm + 128 * 68;   // [128k][68]
    int c0 = blockIdx.x * 64;
    int t0 = blockIdx.y * 64;
    int tid = threadIdx.x;
    for (int idx = tid; idx < 64 * 128; idx += 256) {
        int r = idx >> 7, k = idx & 127;
        aT[k * 68 + r] = A[(t0 + r) * 128 + k];
        wT[k * 68 + r] = Wrows[(c0 + r) * 128 + k];
    }
    __syncthreads();
    int ty = tid >> 4, tx = tid & 15;
    float acc[4][4] = {};
    #pragma unroll 4
    for (int k = 0; k < 128; k++) {
        float4 av = *(const float4*)&aT[k * 68 + 4 * ty];
        float4 bv = *(const float4*)&wT[k * 68 + 4 * tx];
        float a[4] = {av.x, av.y, av.z, av.w};
        float c[4] = {bv.x, bv.y, bv.z, bv.w};
        #pragma unroll
        for (int i = 0; i < 4; i++)
            #pragma unroll
            for (int j = 0; j < 4; j++) acc[i][j] = fmaf(a[i], c[j], acc[i][j]);
    }
    #pragma unroll
    for (int i = 0; i < 4; i++) {
        int token = t0 + 4 * ty + i;
        #pragma unroll
        for (int j = 0; j < 4; j++) {
            int c = c0 + 4 * tx + j;
            float val = acc[i][j] + __ldg(&bias[c]);
            if (mode == 0) {
                float* dst = (c < 128) ? g_q : ((c < 256) ? g_k : g_v);
                dst[token * 128 + (c & 127)] = val;
            } else if (mode == 1) {
                g_q[token * 128 + c] = 0.5f * val * (1.0f + erff(val * 0.70710678118654752f));
            } else {
                out[token * 128 + c] = val;
            }
        }
    }
}

// ---------------- pairwise distance tiles + global sum ----------------
// grid (64 jt, 64 it, BATCH), 256 threads, dyn smem = 2*128*68*4 = 69632 B
__global__ void __launch_bounds__(256) k_dist(const float* __restrict__ x) {
    extern __shared__ float sm[];
    float* xiT = sm;              // [128][68] k-major
    float* xjT = sm + 128 * 68;
    int b  = blockIdx.z;
    int i0 = blockIdx.y * 64, j0 = blockIdx.x * 64;
    int tid = threadIdx.x;
    for (int idx = tid; idx < 64 * 128; idx += 256) {
        int r = idx >> 7, k = idx & 127;
        xiT[k * 68 + r] = x[(b * SEQ + i0 + r) * 128 + k];
        xjT[k * 68 + r] = x[(b * SEQ + j0 + r) * 128 + k];
    }
    __syncthreads();
    int ty = tid >> 4, tx = tid & 15;
    float acc[4][4] = {};
    #pragma unroll 4
    for (int k = 0; k < 128; k++) {
        float4 av = *(const float4*)&xiT[k * 68 + 4 * ty];
        float4 bv = *(const float4*)&xjT[k * 68 + 4 * tx];
        float a[4] = {av.x, av.y, av.z, av.w};
        float c[4] = {bv.x, bv.y, bv.z, bv.w};
        #pragma unroll
        for (int i = 0; i < 4; i++)
            #pragma unroll
            for (int j = 0; j < 4; j++) acc[i][j] = fmaf(a[i], c[j], acc[i][j]);
    }
    float sqi[4], sqj[4];
    #pragma unroll
    for (int i = 0; i < 4; i++) {
        sqi[i] = g_sq[b * SEQ + i0 + 4 * ty + i];
        sqj[i] = g_sq[b * SEQ + j0 + 4 * tx + i];
    }
    float lsum = 0.f;
    #pragma unroll
    for (int i = 0; i < 4; i++) {
        float dv[4];
        #pragma unroll
        for (int j = 0; j < 4; j++) {
            float d2 = sqi[i] + sqj[j] - 2.f * acc[i][j];
            float dd = sqrtf(fmaxf(d2, 0.f));
            dv[j] = dd; lsum += dd;
        }
        size_t base = ((size_t)(b * SEQ + i0 + 4 * ty + i)) * SEQ + j0 + 4 * tx;
        __half2* dp = (__half2*)(g_dist + base);
        dp[0] = __floats2half2_rn(dv[0], dv[1]);
        dp[1] = __floats2half2_rn(dv[2], dv[3]);
    }
    #pragma unroll
    for (int o = 16; o; o >>= 1) lsum += __shfl_xor_sync(0xffffffffu, lsum, o);
    __shared__ float rsum[8];
    if ((tid & 31) == 0) rsum[tid >> 5] = lsum;
    __syncthreads();
    if (tid == 0) {
        float tot = 0.f;
        #pragma unroll
        for (int w = 0; w < 8; w++) tot += rsum[w];
        atomicAdd(&g_sum_spe, (double)tot);
    }
}

// ---------------- finalize sigmas + spatial LUT ----------------
__global__ void k_finalize() {
    int t = threadIdx.x;
    __shared__ double red[256];
    double local = 0.0;
    for (int idx = t; idx < 64 * 64; idx += 256) {
        int adx = idx >> 6, ady = idx & 63;
        double cx = adx ? 2.0 * (64 - adx) : 64.0;
        double cy = ady ? 2.0 * (64 - ady) : 64.0;
        local += cx * cy * sqrt((double)(adx * adx + ady * ady));
    }
    red[t] = local; __syncthreads();
    for (int s = 128; s; s >>= 1) { if (t < s) red[t] += red[t + s]; __syncthreads(); }
    __shared__ float inv_spa;
    if (t == 0) {
        double sig_spa = red[0] / ((double)SEQ * (double)SEQ);
        inv_spa = (float)(1.0 / (2.0 * sig_spa * sig_spa));
        double sig_spe = g_sum_spe / ((double)BATCH * (double)SEQ * (double)SEQ);
        g_inv2s2_spe = (float)(1.0 / (2.0 * sig_spe * sig_spe));
    }
    __syncthreads();
    float iv = inv_spa;
    for (int idx = t; idx < 64 * 64; idx += 256) {
        int adx = idx >> 6, ady = idx & 63;
        g_spa[idx] = expf(-sqrtf((float)(adx * adx + ady * ady)) * iv);
    }
}

// ---------------- fused masked flash attention (both heads/CTA) ----------------
// grid (64 row-tiles, BATCH), 256 threads, dyn smem = 138240 B
__global__ void __launch_bounds__(256, 1) k_flash() {
    extern __shared__ float sm[];
    float* qiT = sm;                      // [128][68]
    float* kjT = qiT + 128 * 68;          // [128][68]
    float* vs  = kjT + 128 * 68;          // [64][132]
    float* ps  = vs + 64 * 132;           // [2][64][68]
    int b  = blockIdx.y;
    int i0 = blockIdx.x * 64;
    int tid = threadIdx.x;
    int ty = tid >> 4, tx = tid & 15;
    int myhead = tx >> 3;
    int d0 = tx * 8;

    for (int idx = tid; idx < 64 * 128; idx += 256) {
        int r = idx >> 7, k = idx & 127;
        qiT[k * 68 + r] = g_q[(b * SEQ + i0 + r) * 128 + k];
    }
    float inv_spe = g_inv2s2_spe;
    float o[4][8] = {};
    float mrun[2][4], lrun[2][4];
    #pragma unroll
    for (int h = 0; h < 2; h++)
        #pragma unroll
        for (int i = 0; i < 4; i++) { mrun[h][i] = -1e30f; lrun[h][i] = 0.f; }
    int ig[4], gxi[4], gyi[4];
    #pragma unroll
    for (int i = 0; i < 4; i++) {
        ig[i] = i0 + 4 * ty + i; gxi[i] = ig[i] >> 6; gyi[i] = ig[i] & 63;
    }

    for (int jt = 0; jt < 64; jt++) {
        int j0 = jt * 64;
        __syncthreads();
        for (int idx = tid; idx < 64 * 128; idx += 256) {
            int r = idx >> 7, k = idx & 127;
            kjT[k * 68 + r]  = g_k[(b * SEQ + j0 + r) * 128 + k];
            vs[r * 132 + k]  = g_v[(b * SEQ + j0 + r) * 128 + k];
        }
        __syncthreads();

        float s0[4][4] = {}, s1[4][4] = {};
        #pragma unroll 4
        for (int k = 0; k < 64; k++) {
            float4 av = *(const float4*)&qiT[k * 68 + 4 * ty];
            float4 bv = *(const float4*)&kjT[k * 68 + 4 * tx];
            float a[4] = {av.x, av.y, av.z, av.w};
            float c[4] = {bv.x, bv.y, bv.z, bv.w};
            #pragma unroll
            for (int i = 0; i < 4; i++)
                #pragma unroll
                for (int j = 0; j < 4; j++) s0[i][j] = fmaf(a[i], c[j], s0[i][j]);
        }
        #pragma unroll 4
        for (int k = 64; k < 128; k++) {
            float4 av = *(const float4*)&qiT[k * 68 + 4 * ty];
            float4 bv = *(const float4*)&kjT[k * 68 + 4 * tx];
            float a[4] = {av.x, av.y, av.z, av.w};
            float c[4] = {bv.x, bv.y, bv.z, bv.w};
            #pragma unroll
            for (int i = 0; i < 4; i++)
                #pragma unroll
                for (int j = 0; j < 4; j++) s1[i][j] = fmaf(a[i], c[j], s1[i][j]);
        }

        float wm[4][4];
        #pragma unroll
        for (int i = 0; i < 4; i++) {
            size_t base = ((size_t)(b * SEQ + ig[i])) * SEQ + j0 + 4 * tx;
            const __half2* dp = (const __half2*)(g_dist + base);
            __half2 h0 = dp[0], h1 = dp[1];
            float dv[4] = { __low2float(h0), __high2float(h0),
                            __low2float(h1), __high2float(h1) };
            #pragma unroll
            for (int j = 0; j < 4; j++) {
                int jg = j0 + 4 * tx + j;
                int adx = abs(gxi[i] - (jg >> 6));
                int ady = abs(gyi[i] - (jg & 63));
                float spa = __ldg(&g_spa[adx * 64 + ady]);
                wm[i][j] = spa * __expf(-dv[j] * inv_spe);
            }
        }

        #pragma unroll
        for (int h = 0; h < 2; h++) {
            float (*sp)[4] = h ? s1 : s0;
            #pragma unroll
            for (int i = 0; i < 4; i++) {
                float p[4]; float mx = -1e30f;
                #pragma unroll
                for (int j = 0; j < 4; j++) {
                    float sc = sp[i][j] * SCALE * wm[i][j];
                    p[j] = sc; mx = fmaxf(mx, sc);
                }
                #pragma unroll
                for (int off = 8; off; off >>= 1)
                    mx = fmaxf(mx, __shfl_xor_sync(0xffffffffu, mx, off));
                float mold = mrun[h][i];
                float mnew = fmaxf(mold, mx);
                float corr = __expf(mold - mnew);
                float rs = 0.f;
                #pragma unroll
                for (int j = 0; j < 4; j++) { p[j] = __expf(p[j] - mnew); rs += p[j]; }
                #pragma unroll
                for (int off = 8; off; off >>= 1)
                    rs += __shfl_xor_sync(0xffffffffu, rs, off);
                lrun[h][i] = lrun[h][i] * corr + rs;
                mrun[h][i] = mnew;
                float* pr = ps + (h * 64 + 4 * ty + i) * 68 + 4 * tx;
                pr[0] = p[0]; pr[1] = p[1]; pr[2] = p[2]; pr[3] = p[3];
                if (myhead == h) {
                    #pragma unroll
                    for (int d = 0; d < 8; d++) o[i][d] *= corr;
                }
            }
        }
        __syncthreads();

        const float* psh = ps + myhead * 64 * 68;
        #pragma unroll 4
        for (int k = 0; k < 64; k++) {
            float4 v0 = *(const float4*)&vs[k * 132 + d0];
            float4 v1 = *(const float4*)&vs[k * 132 + d0 + 4];
            #pragma unroll
            for (int i = 0; i < 4; i++) {
                float pv = psh[(4 * ty + i) * 68 + k];
                o[i][0] = fmaf(pv, v0.x, o[i][0]);
                o[i][1] = fmaf(pv, v0.y, o[i][1]);
                o[i][2] = fmaf(pv, v0.z, o[i][2]);
                o[i][3] = fmaf(pv, v0.w, o[i][3]);
                o[i][4] = fmaf(pv, v1.x, o[i][4]);
                o[i][5] = fmaf(pv, v1.y, o[i][5]);
                o[i][6] = fmaf(pv, v1.z, o[i][6]);
                o[i][7] = fmaf(pv, v1.w, o[i][7]);
            }
        }
    }

    #pragma unroll
    for (int i = 0; i < 4; i++) {
        float linv = 1.f / lrun[myhead][i];
        float* dst = g_attn + (b * SEQ + ig[i]) * 128 + d0;
        #pragma unroll
        for (int d = 0; d < 8; d++) dst[d] = o[i][d] * linv;
    }
}

// ---------------- launch ----------------
extern "C" void kernel_launch(void* const* d_in, const int* in_sizes, int n_in,
                              void* d_out, int out_size) {
    const float* x     = (const float*)d_in[0];
    const float* v_qkv = (const float*)d_in[1];
    const float* g_qkv_ = (const float*)d_in[2];
    const float* b_qkv = (const float*)d_in[3];
    const float* v_ff1 = (const float*)d_in[4];
    const float* g_ff1 = (const float*)d_in[5];
    const float* b_ff1 = (const float*)d_in[6];
    const float* v_ff2 = (const float*)d_in[7];
    const float* g_ff2 = (const float*)d_in[8];
    const float* b_ff2 = (const float*)d_in[9];
    float* out = (float*)d_out;

    const int GEMM_SMEM = 2 * 128 * 68 * 4;
    cudaFuncSetAttribute(k_gemm64, cudaFuncAttributeMaxDynamicSharedMemorySize, GEMM_SMEM);
    cudaFuncSetAttribute(k_dist,   cudaFuncAttributeMaxDynamicSharedMemorySize, GEMM_SMEM);
    cudaFuncSetAttribute(k_flash,  cudaFuncAttributeMaxDynamicSharedMemorySize,
                         (128 * 68 + 128 * 68 + 64 * 132 + 2 * 64 * 68) * 4);

    float* Wdev = nullptr;
    cudaGetSymbolAddress((void**)&Wdev, g_W);

    k_init<<<1, 1>>>();
    k_weights<<<640, 128>>>(v_qkv, g_qkv_, v_ff1, g_ff1, v_ff2, g_ff2);
    k_sq<<<BATCH * SEQ / 8, 256>>>(x);
    // QKV projection: 384 output cols
    k_gemm64<<<dim3(6, BATCH * SEQ / 64), 256, GEMM_SMEM>>>(x, Wdev, b_qkv, nullptr, 0);
    k_dist<<<dim3(64, 64, BATCH), 256, GEMM_SMEM>>>(x);
    k_finalize<<<1, 256>>>();
    k_flash<<<dim3(64, BATCH), 256, (128 * 68 + 128 * 68 + 64 * 132 + 2 * 64 * 68) * 4>>>();
    // FF1 (+GELU) into g_q (dead after flash), then FF2 into d_out
    float* attn_dev = nullptr; cudaGetSymbolAddress((void**)&attn_dev, g_attn);
    float* h1_dev   = nullptr; cudaGetSymbolAddress((void**)&h1_dev, g_q);
    k_gemm64<<<dim3(2, BATCH * SEQ / 64), 256, GEMM_SMEM>>>(attn_dev, Wdev + 384 * 128, b_ff1, nullptr, 1);
    k_gemm64<<<dim3(2, BATCH * SEQ / 64), 256, GEMM_SMEM>>>(h1_dev, Wdev + 512 * 128, b_ff2, out, 2);
}

// round 4
// speedup vs baseline: 4.4722x; 1.7024x over previous
#include <cuda_runtime.h>
#include <cuda_fp16.h>
#include <math.h>
#include <stdint.h>

#define BATCH 2
#define SEQ   4096
#define DIM   128
#define SCALE 0.125f   // 64^-0.5

// ---------------- device scratch ----------------
__device__ float  g_W[640 * 128];            // rows: 0..383 qkv, 384..511 ff1, 512..639 ff2
__device__ float  g_q[BATCH * SEQ * DIM];    // reused as h1 after flash
__device__ float  g_k[BATCH * SEQ * DIM];
__device__ float  g_vT[DIM * BATCH * SEQ];   // [d][global token]
__device__ float  g_sq[BATCH * SEQ];
__device__ __half g_dist[(size_t)BATCH * SEQ * SEQ];   // 67 MB fp16 distances
__device__ double g_sum_spe;
__device__ float  g_inv2s2_spe;
__device__ float  g_spa[64 * 64];
__device__ float  g_attn[BATCH * SEQ * DIM];

// ---------------- tf32 helpers ----------------
__device__ __forceinline__ uint32_t f2tf(float f) {
    uint32_t r; asm("cvt.rna.tf32.f32 %0, %1;" : "=r"(r) : "f"(f)); return r;
}
__device__ __forceinline__ void split_tf(float f, uint32_t& hi, uint32_t& lo) {
    hi = f2tf(f);
    lo = f2tf(f - __uint_as_float(hi));
}
__device__ __forceinline__ void mma8(float* c, const uint32_t* a, uint32_t b0, uint32_t b1) {
    asm volatile("mma.sync.aligned.m16n8k8.row.col.f32.tf32.tf32.f32 "
                 "{%0,%1,%2,%3},{%4,%5,%6,%7},{%8,%9},{%0,%1,%2,%3};"
                 : "+f"(c[0]), "+f"(c[1]), "+f"(c[2]), "+f"(c[3])
                 : "r"(a[0]), "r"(a[1]), "r"(a[2]), "r"(a[3]), "r"(b0), "r"(b1));
}

// ---------------- init ----------------
__global__ void k_init() { g_sum_spe = 0.0; }

// ---------------- weight norm ----------------
__global__ void k_weights(const float* __restrict__ vq, const float* __restrict__ gq,
                          const float* __restrict__ v1, const float* __restrict__ g1,
                          const float* __restrict__ v2, const float* __restrict__ g2) {
    int r = blockIdx.x, t = threadIdx.x;
    const float* v; float g;
    if (r < 384)      { v = vq + r * 128;        g = gq[r]; }
    else if (r < 512) { v = v1 + (r - 384) * 128; g = g1[r - 384]; }
    else              { v = v2 + (r - 512) * 128; g = g2[r - 512]; }
    float val = v[t];
    float ss = val * val;
    #pragma unroll
    for (int o = 16; o; o >>= 1) ss += __shfl_xor_sync(0xffffffffu, ss, o);
    __shared__ float ws[4];
    if ((t & 31) == 0) ws[t >> 5] = ss;
    __syncthreads();
    float tot = ws[0] + ws[1] + ws[2] + ws[3];
    g_W[r * 128 + t] = val * (g / sqrtf(tot));
}

// ---------------- per-token ||x||^2 ----------------
__global__ void k_sq(const float* __restrict__ x) {
    int token = blockIdx.x * 8 + (threadIdx.x >> 5);
    int lane  = threadIdx.x & 31;
    const float4* xp = (const float4*)(x + token * 128);
    float4 a = xp[lane];
    float ss = a.x * a.x + a.y * a.y + a.z * a.z + a.w * a.w;
    #pragma unroll
    for (int o = 16; o; o >>= 1) ss += __shfl_xor_sync(0xffffffffu, ss, o);
    if (lane == 0) g_sq[token] = ss;
}

// ---------------- tiled projection GEMM (scalar fp32, exact) ----------------
// mode 0: qkv scatter (v transposed); mode 1: GELU -> g_q; mode 2: plain -> out
__global__ void __launch_bounds__(256) k_gemm64(const float* __restrict__ A,
                                                const float* __restrict__ Wrows,
                                                const float* __restrict__ bias,
                                                float* __restrict__ out, int mode) {
    extern __shared__ float sm[];
    float* aT = sm;
    float* wT = sm + 128 * 68;
    int c0 = blockIdx.x * 64;
    int t0 = blockIdx.y * 64;
    int tid = threadIdx.x;
    for (int idx = tid; idx < 64 * 128; idx += 256) {
        int r = idx >> 7, k = idx & 127;
        aT[k * 68 + r] = A[(t0 + r) * 128 + k];
        wT[k * 68 + r] = Wrows[(c0 + r) * 128 + k];
    }
    __syncthreads();
    int ty = tid >> 4, tx = tid & 15;
    float acc[4][4] = {};
    #pragma unroll 4
    for (int k = 0; k < 128; k++) {
        float4 av = *(const float4*)&aT[k * 68 + 4 * ty];
        float4 bv = *(const float4*)&wT[k * 68 + 4 * tx];
        float a[4] = {av.x, av.y, av.z, av.w};
        float c[4] = {bv.x, bv.y, bv.z, bv.w};
        #pragma unroll
        for (int i = 0; i < 4; i++)
            #pragma unroll
            for (int j = 0; j < 4; j++) acc[i][j] = fmaf(a[i], c[j], acc[i][j]);
    }
    #pragma unroll
    for (int i = 0; i < 4; i++) {
        int token = t0 + 4 * ty + i;
        #pragma unroll
        for (int j = 0; j < 4; j++) {
            int c = c0 + 4 * tx + j;
            float val = acc[i][j] + __ldg(&bias[c]);
            if (mode == 0) {
                if (c < 128)      g_q[token * 128 + c] = val;
                else if (c < 256) g_k[token * 128 + (c - 128)] = val;
                else              g_vT[(size_t)(c - 256) * (BATCH * SEQ) + token] = val;
            } else if (mode == 1) {
                g_q[token * 128 + c] = 0.5f * val * (1.0f + erff(val * 0.70710678118654752f));
            } else {
                out[token * 128 + c] = val;
            }
        }
    }
}

// ---------------- pairwise distance via tf32 MMA ----------------
// grid (32 jt, 32 it, BATCH), 256 threads, 128x128 tile, smem 135168 B
__global__ void __launch_bounds__(256) k_dist(const float* __restrict__ x) {
    extern __shared__ float sm[];
    float* xi = sm;              // [128][132]
    float* xj = sm + 128 * 132;  // [128][132]
    int b = blockIdx.z, i0 = blockIdx.y * 128, j0 = blockIdx.x * 128;
    int tid = threadIdx.x;
    for (int fi = tid; fi < 4096; fi += 256) {   // 128*128/4 float4
        int r = fi >> 5, c4 = (fi & 31) * 4;
        *(float4*)&xi[r * 132 + c4] = *(const float4*)&x[(size_t)(b * SEQ + i0 + r) * 128 + c4];
        *(float4*)&xj[r * 132 + c4] = *(const float4*)&x[(size_t)(b * SEQ + j0 + r) * 128 + c4];
    }
    __syncthreads();
    int lane = tid & 31, w = tid >> 5;
    int wr = w >> 1, wc = w & 1;
    int g = lane >> 2, t = lane & 3;
    float c[2][8][4] = {};
    #pragma unroll 1
    for (int ks = 0; ks < 16; ks++) {
        uint32_t A[2][4];
        #pragma unroll
        for (int mt = 0; mt < 2; mt++)
            #pragma unroll
            for (int e = 0; e < 4; e++)
                A[mt][e] = f2tf(xi[(32 * wr + 16 * mt + g + 8 * (e & 1)) * 132 + 8 * ks + t + 4 * (e >> 1)]);
        #pragma unroll
        for (int nt = 0; nt < 8; nt++) {
            int row = (64 * wc + 8 * nt + g) * 132 + 8 * ks + t;
            uint32_t b0 = f2tf(xj[row]);
            uint32_t b1 = f2tf(xj[row + 4]);
            mma8(c[0][nt], A[0], b0, b1);
            mma8(c[1][nt], A[1], b0, b1);
        }
    }
    float lsum = 0.f;
    #pragma unroll
    for (int mt = 0; mt < 2; mt++) {
        int ir0 = i0 + 32 * wr + 16 * mt + g;
        float sqi0 = __ldg(&g_sq[b * SEQ + ir0]);
        float sqi1 = __ldg(&g_sq[b * SEQ + ir0 + 8]);
        #pragma unroll
        for (int nt = 0; nt < 8; nt++) {
            int jc = j0 + 64 * wc + 8 * nt + 2 * t;
            float sj0 = __ldg(&g_sq[b * SEQ + jc]);
            float sj1 = __ldg(&g_sq[b * SEQ + jc + 1]);
            float d00 = sqrtf(fmaxf(sqi0 + sj0 - 2.f * c[mt][nt][0], 0.f));
            float d01 = sqrtf(fmaxf(sqi0 + sj1 - 2.f * c[mt][nt][1], 0.f));
            float d10 = sqrtf(fmaxf(sqi1 + sj0 - 2.f * c[mt][nt][2], 0.f));
            float d11 = sqrtf(fmaxf(sqi1 + sj1 - 2.f * c[mt][nt][3], 0.f));
            lsum += d00 + d01 + d10 + d11;
            *(__half2*)&g_dist[(size_t)(b * SEQ + ir0) * SEQ + jc]     = __floats2half2_rn(d00, d01);
            *(__half2*)&g_dist[(size_t)(b * SEQ + ir0 + 8) * SEQ + jc] = __floats2half2_rn(d10, d11);
        }
    }
    #pragma unroll
    for (int o = 16; o; o >>= 1) lsum += __shfl_xor_sync(0xffffffffu, lsum, o);
    __shared__ float rsum[8];
    if (lane == 0) rsum[w] = lsum;
    __syncthreads();
    if (tid == 0) {
        float tot = 0.f;
        #pragma unroll
        for (int i = 0; i < 8; i++) tot += rsum[i];
        atomicAdd(&g_sum_spe, (double)tot);
    }
}

// ---------------- finalize sigmas + spatial LUT ----------------
__global__ void k_finalize() {
    int t = threadIdx.x;
    __shared__ double red[256];
    double local = 0.0;
    for (int idx = t; idx < 64 * 64; idx += 256) {
        int adx = idx >> 6, ady = idx & 63;
        double cx = adx ? 2.0 * (64 - adx) : 64.0;
        double cy = ady ? 2.0 * (64 - ady) : 64.0;
        local += cx * cy * sqrt((double)(adx * adx + ady * ady));
    }
    red[t] = local; __syncthreads();
    for (int s = 128; s; s >>= 1) { if (t < s) red[t] += red[t + s]; __syncthreads(); }
    __shared__ float inv_spa;
    if (t == 0) {
        double sig_spa = red[0] / ((double)SEQ * (double)SEQ);
        inv_spa = (float)(1.0 / (2.0 * sig_spa * sig_spa));
        double sig_spe = g_sum_spe / ((double)BATCH * (double)SEQ * (double)SEQ);
        g_inv2s2_spe = (float)(1.0 / (2.0 * sig_spe * sig_spe));
    }
    __syncthreads();
    float iv = inv_spa;
    for (int idx = t; idx < 64 * 64; idx += 256) {
        int adx = idx >> 6, ady = idx & 63;
        g_spa[idx] = expf(-sqrtf((float)(adx * adx + ady * ady)) * iv);
    }
}

// ---------------- flash attention, 3xTF32 tensor-core ----------------
// smem layout (floats):
#define KH_OFF 0
#define KL_OFF 8448          // 64*132
#define VH_OFF 16896
#define VL_OFF 25600         // + 128*68
#define PH_OFF 34304
#define PL_OFF 43008         // + 2*64*68
#define WS_OFF 51712
#define FLASH_SMEM_FLOATS 56064   // + 64*68
__global__ void __launch_bounds__(256, 1) k_flash() {
    extern __shared__ float sm[];
    float* smKH = sm + KH_OFF;   // [64 tok][132 dims] hi
    float* smKL = sm + KL_OFF;
    float* smVH = sm + VH_OFF;   // [128 d][68 j] hi
    float* smVL = sm + VL_OFF;
    float* smPH = sm + PH_OFF;   // [2][64 row][68 col]
    float* smPL = sm + PL_OFF;
    float* smWS = sm + WS_OFF;   // [64 i][68 j] combined mask
    int b  = blockIdx.y;
    int i0 = blockIdx.x * 64;
    int tid = threadIdx.x;
    int lane = tid & 31, w = tid >> 5;
    int h = w >> 2, ms = w & 3;           // head, m-strip
    int g = lane >> 2, t = lane & 3;
    float inv_spe = g_inv2s2_spe;

    // preload Q fragments (hi/lo) into registers — reused across all jtiles
    uint32_t qh[8][4], ql[8][4];
    #pragma unroll
    for (int ks = 0; ks < 8; ks++)
        #pragma unroll
        for (int e = 0; e < 4; e++) {
            int row = i0 + 16 * ms + g + (e & 1) * 8;
            int col = h * 64 + ks * 8 + t + (e >> 1) * 4;
            split_tf(g_q[(size_t)(b * SEQ + row) * 128 + col], qh[ks][e], ql[ks][e]);
        }

    float co[8][4] = {};
    float m0 = -1e30f, m1 = -1e30f, l0 = 0.f, l1 = 0.f;
    int r0loc = 16 * ms + g;            // local row for c0,c1
    float* myPH = smPH + (h * 64) * 68;
    float* myPL = smPL + (h * 64) * 68;

    for (int jt = 0; jt < 64; jt++) {
        int j0 = jt * 64;
        __syncthreads();
        // --- load K tile split hi/lo ---
        for (int fi = tid; fi < 2048; fi += 256) {   // 64*128/4
            int r = fi >> 5, c4 = (fi & 31) * 4;
            float4 kv = *(const float4*)&g_k[(size_t)(b * SEQ + j0 + r) * 128 + c4];
            uint4 h4, l4;
            split_tf(kv.x, h4.x, l4.x); split_tf(kv.y, h4.y, l4.y);
            split_tf(kv.z, h4.z, l4.z); split_tf(kv.w, h4.w, l4.w);
            *(uint4*)&smKH[r * 132 + c4] = h4;
            *(uint4*)&smKL[r * 132 + c4] = l4;
        }
        // --- load V^T tile split hi/lo ---
        for (int fi = tid; fi < 2048; fi += 256) {   // 128*64/4
            int d = fi >> 4, j4 = (fi & 15) * 4;
            float4 vv = *(const float4*)&g_vT[(size_t)d * (BATCH * SEQ) + b * SEQ + j0 + j4];
            uint4 h4, l4;
            split_tf(vv.x, h4.x, l4.x); split_tf(vv.y, h4.y, l4.y);
            split_tf(vv.z, h4.z, l4.z); split_tf(vv.w, h4.w, l4.w);
            *(uint4*)&smVH[d * 68 + j4] = h4;
            *(uint4*)&smVL[d * 68 + j4] = l4;
        }
        // --- combined mask tile: spe * spa ---
        for (int ii = tid; ii < 4096; ii += 256) {
            int i = ii >> 6, j = ii & 63;
            float dd = __half2float(g_dist[(size_t)(b * SEQ + i0 + i) * SEQ + j0 + j]);
            int gi = i0 + i, gj = j0 + j;
            int adx = abs((gi >> 6) - (gj >> 6));
            int ady = abs((gi & 63) - (gj & 63));
            smWS[i * 68 + j] = __ldg(&g_spa[adx * 64 + ady]) * __expf(-dd * inv_spe);
        }
        __syncthreads();

        // --- QK^T 3xTF32 ---
        float cs[8][4] = {};
        #pragma unroll
        for (int ks = 0; ks < 8; ks++) {
            #pragma unroll
            for (int nt = 0; nt < 8; nt++) {
                int base = (8 * nt + g) * 132 + h * 64 + 8 * ks + t;
                uint32_t bh0 = __float_as_uint(smKH[base]);
                uint32_t bh1 = __float_as_uint(smKH[base + 4]);
                uint32_t bl0 = __float_as_uint(smKL[base]);
                uint32_t bl1 = __float_as_uint(smKL[base + 4]);
                mma8(cs[nt], qh[ks], bh0, bh1);
                mma8(cs[nt], qh[ks], bl0, bl1);
                mma8(cs[nt], ql[ks], bh0, bh1);
            }
        }

        // --- mask + online softmax ---
        float mloc0 = -1e30f, mloc1 = -1e30f;
        #pragma unroll
        for (int nt = 0; nt < 8; nt++) {
            int col = 8 * nt + 2 * t;
            float2 wa = *(const float2*)&smWS[r0loc * 68 + col];
            float2 wb = *(const float2*)&smWS[(r0loc + 8) * 68 + col];
            cs[nt][0] *= SCALE * wa.x; cs[nt][1] *= SCALE * wa.y;
            cs[nt][2] *= SCALE * wb.x; cs[nt][3] *= SCALE * wb.y;
            mloc0 = fmaxf(mloc0, fmaxf(cs[nt][0], cs[nt][1]));
            mloc1 = fmaxf(mloc1, fmaxf(cs[nt][2], cs[nt][3]));
        }
        #pragma unroll
        for (int o = 1; o <= 2; o <<= 1) {
            mloc0 = fmaxf(mloc0, __shfl_xor_sync(0xffffffffu, mloc0, o));
            mloc1 = fmaxf(mloc1, __shfl_xor_sync(0xffffffffu, mloc1, o));
        }
        float mn0 = fmaxf(m0, mloc0), mn1 = fmaxf(m1, mloc1);
        float corr0 = __expf(m0 - mn0), corr1 = __expf(m1 - mn1);
        m0 = mn0; m1 = mn1;
        float rs0 = 0.f, rs1 = 0.f;
        #pragma unroll
        for (int nt = 0; nt < 8; nt++) {
            float p0 = __expf(cs[nt][0] - mn0), p1 = __expf(cs[nt][1] - mn0);
            float p2 = __expf(cs[nt][2] - mn1), p3 = __expf(cs[nt][3] - mn1);
            rs0 += p0 + p1; rs1 += p2 + p3;
            uint2 uh, ul;
            split_tf(p0, uh.x, ul.x); split_tf(p1, uh.y, ul.y);
            int col = 8 * nt + 2 * t;
            *(uint2*)&myPH[r0loc * 68 + col] = uh;
            *(uint2*)&myPL[r0loc * 68 + col] = ul;
            split_tf(p2, uh.x, ul.x); split_tf(p3, uh.y, ul.y);
            *(uint2*)&myPH[(r0loc + 8) * 68 + col] = uh;
            *(uint2*)&myPL[(r0loc + 8) * 68 + col] = ul;
        }
        #pragma unroll
        for (int o = 1; o <= 2; o <<= 1) {
            rs0 += __shfl_xor_sync(0xffffffffu, rs0, o);
            rs1 += __shfl_xor_sync(0xffffffffu, rs1, o);
        }
        l0 = l0 * corr0 + rs0;
        l1 = l1 * corr1 + rs1;
        #pragma unroll
        for (int nt = 0; nt < 8; nt++) {
            co[nt][0] *= corr0; co[nt][1] *= corr0;
            co[nt][2] *= corr1; co[nt][3] *= corr1;
        }
        __syncwarp();

        // --- PV 3xTF32 ---
        #pragma unroll
        for (int ks = 0; ks < 8; ks++) {
            uint32_t ah[4], al[4];
            #pragma unroll
            for (int e = 0; e < 4; e++) {
                int idx = (r0loc + (e & 1) * 8) * 68 + 8 * ks + t + (e >> 1) * 4;
                ah[e] = __float_as_uint(myPH[idx]);
                al[e] = __float_as_uint(myPL[idx]);
            }
            #pragma unroll
            for (int nt = 0; nt < 8; nt++) {
                int base = (h * 64 + 8 * nt + g) * 68 + 8 * ks + t;
                uint32_t bh0 = __float_as_uint(smVH[base]);
                uint32_t bh1 = __float_as_uint(smVH[base + 4]);
                uint32_t bl0 = __float_as_uint(smVL[base]);
                uint32_t bl1 = __float_as_uint(smVL[base + 4]);
                mma8(co[nt], ah, bh0, bh1);
                mma8(co[nt], ah, bl0, bl1);
                mma8(co[nt], al, bh0, bh1);
            }
        }
    }

    // --- epilogue ---
    float li0 = 1.f / l0, li1 = 1.f / l1;
    #pragma unroll
    for (int nt = 0; nt < 8; nt++) {
        int col = h * 64 + 8 * nt + 2 * t;
        int row0 = b * SEQ + i0 + r0loc;
        float2 o0 = {co[nt][0] * li0, co[nt][1] * li0};
        float2 o1 = {co[nt][2] * li1, co[nt][3] * li1};
        *(float2*)&g_attn[(size_t)row0 * 128 + col] = o0;
        *(float2*)&g_attn[(size_t)(row0 + 8) * 128 + col] = o1;
    }
}

// ---------------- launch ----------------
extern "C" void kernel_launch(void* const* d_in, const int* in_sizes, int n_in,
                              void* d_out, int out_size) {
    const float* x      = (const float*)d_in[0];
    const float* v_qkv  = (const float*)d_in[1];
    const float* g_qkv_ = (const float*)d_in[2];
    const float* b_qkv  = (const float*)d_in[3];
    const float* v_ff1  = (const float*)d_in[4];
    const float* g_ff1  = (const float*)d_in[5];
    const float* b_ff1  = (const float*)d_in[6];
    const float* v_ff2  = (const float*)d_in[7];
    const float* g_ff2  = (const float*)d_in[8];
    const float* b_ff2  = (const float*)d_in[9];
    float* out = (float*)d_out;

    const int GEMM_SMEM  = 2 * 128 * 68 * 4;        // 69632
    const int DIST_SMEM  = 2 * 128 * 132 * 4;       // 135168
    const int FLASH_SMEM = FLASH_SMEM_FLOATS * 4;   // 224256
    cudaFuncSetAttribute(k_gemm64, cudaFuncAttributeMaxDynamicSharedMemorySize, GEMM_SMEM);
    cudaFuncSetAttribute(k_dist,   cudaFuncAttributeMaxDynamicSharedMemorySize, DIST_SMEM);
    cudaFuncSetAttribute(k_flash,  cudaFuncAttributeMaxDynamicSharedMemorySize, FLASH_SMEM);

    float* Wdev = nullptr;     cudaGetSymbolAddress((void**)&Wdev, g_W);
    float* attn_dev = nullptr; cudaGetSymbolAddress((void**)&attn_dev, g_attn);
    float* h1_dev = nullptr;   cudaGetSymbolAddress((void**)&h1_dev, g_q);

    k_init<<<1, 1>>>();
    k_weights<<<640, 128>>>(v_qkv, g_qkv_, v_ff1, g_ff1, v_ff2, g_ff2);
    k_sq<<<BATCH * SEQ / 8, 256>>>(x);
    k_gemm64<<<dim3(6, BATCH * SEQ / 64), 256, GEMM_SMEM>>>(x, Wdev, b_qkv, nullptr, 0);
    k_dist<<<dim3(32, 32, BATCH), 256, DIST_SMEM>>>(x);
    k_finalize<<<1, 256>>>();
    k_flash<<<dim3(64, BATCH), 256, FLASH_SMEM>>>();
    k_gemm64<<<dim3(2, BATCH * SEQ / 64), 256, GEMM_SMEM>>>(attn_dev, Wdev + 384 * 128, b_ff1, nullptr, 1);
    k_gemm64<<<dim3(2, BATCH * SEQ / 64), 256, GEMM_SMEM>>>(h1_dev, Wdev + 512 * 128, b_ff2, out, 2);
}